// round 16
// baseline (speedup 1.0000x reference)
#include <cuda_runtime.h>
#include <cuda_fp16.h>
#include <cstdint>

// Sinkhorn OT: B=1024, N=M=256, <=100 iters (period-2 bit-exact early exit),
// 512 threads/CTA. Thread pair (2i,2i+1) owns row i (half h=tid&1).
// Row pass from 64 regs; col pass over K^T in SMEM (544B pitch, paired
// LDS.128 conflict-free). Cost reconstructed from registers (no 2nd C read).
// NEW: work-stealing batch assignment (atomicAdd counter) to erase
// wave-granularity imbalance from variable early-exit iteration counts;
// setup fused: exp() computed straight into registers, K^T scatter only.

#define BATCH 1024
#define DIM 256
#define MAX_IT 100
#define EPS_DIV 1e-8f
#define KSC_K 16.0f
#define KSC_U 4.0f
#define KSC_V 256.0f
#define UNSC_KTU (1.0f/64.0f)
#define UNSC_KV  (1.0f/4096.0f)
#define NT 512
#define LN16 2.7725887222397812f

#define ROW_B 544            // bytes per K^T row (136 words; 136%32=8)
#define SEG_B 272            // byte offset of half-1 (68 words)
#define OFF_UH  139264       // 256*544 ; half[256] u*4
#define OFF_VH  (OFF_UH + 512)
#define OFF_US  (OFF_VH + 512)
#define OFF_VS  (OFF_US + 1024)
#define OFF_AS  (OFF_VS + 1024)
#define OFF_BS  (OFF_AS + 1024)
#define OFF_RED (OFF_BS + 1024)   // float[16]
#define SMEM_BYTES (OFF_RED + 64)

__device__ float g_partial[BATCH];
__device__ int   g_ctr;

__device__ __forceinline__ __half2 H2(uint32_t w) {
    return *reinterpret_cast<__half2*>(&w);
}

__device__ __forceinline__ float block_sum512(float val, float* red, int tid) {
    #pragma unroll
    for (int o = 16; o > 0; o >>= 1) val += __shfl_xor_sync(0xffffffffu, val, o);
    if ((tid & 31) == 0) red[tid >> 5] = val;
    __syncthreads();
    float t = 0.f;
    #pragma unroll
    for (int w = 0; w < 16; ++w) t += red[w];
    __syncthreads();
    return t;
}

extern "C" __global__ void reset_kernel() { g_ctr = 0; }

extern "C" __global__ void __launch_bounds__(NT, 1)
sinkhorn_kernel(const float* __restrict__ C,
                const float* __restrict__ mp,
                const float* __restrict__ mt)
{
    extern __shared__ unsigned char smem[];
    __half* u_h = (__half*)(smem + OFF_UH);
    __half* v_h = (__half*)(smem + OFF_VH);
    float*  u_s = (float*)(smem + OFF_US);
    float*  v_s = (float*)(smem + OFF_VS);
    float*  a_s = (float*)(smem + OFF_AS);
    float*  b_s = (float*)(smem + OFF_BS);
    float*  red = (float*)(smem + OFF_RED);

    const int tid = threadIdx.x;
    const int r   = tid >> 1;    // my row (0..255)
    const int h   = tid & 1;     // my half of the row

    // ---- work stealing: completion-order batch assignment ----------------
    __shared__ int sh_b;
    if (tid == 0) sh_b = atomicAdd(&g_ctr, 1);
    __syncthreads();
    const int b = sh_b;

    // ---- Phase 1 (fused): exp(-10C)*16 for my half-row -> 64 regs --------
    uint32_t kreg[64];
    {
        const float4* myC = (const float4*)(C + (size_t)b * (DIM * DIM)
                                              + r * DIM + h * 128);
        #pragma unroll
        for (int j = 0; j < 32; ++j) {
            float4 c = myC[j];
            __half2 h0 = __floats2half2_rn(__expf(-10.f * c.x) * KSC_K,
                                           __expf(-10.f * c.y) * KSC_K);
            __half2 h1 = __floats2half2_rn(__expf(-10.f * c.z) * KSC_K,
                                           __expf(-10.f * c.w) * KSC_K);
            kreg[2 * j]     = *(uint32_t*)&h0;
            kreg[2 * j + 1] = *(uint32_t*)&h1;
        }
    }
    float mpv = (tid < 256) ? mp[b * DIM + tid] : 0.f;
    float mtv = (tid < 256) ? mt[b * DIM + tid] : 0.f;

    // ---- scatter K^T into SMEM (disjoint cells; fenced by block_sum) -----
    {
        const int seg_r = r >> 7;
        const int win_r = (r & 127) * 2;
        #pragma unroll 8
        for (int j = 0; j < 64; ++j) {
            __half2 p = H2(kreg[j]);
            int c0 = 128 * h + 2 * j;         // K column = K^T row
            *(__half*)(smem + c0 * ROW_B + seg_r * SEG_B + win_r) = __low2half(p);
            *(__half*)(smem + (c0 + 1) * ROW_B + seg_r * SEG_B + win_r) = __high2half(p);
        }
    }

    // ---- Phase 2: normalize masses, init u (barriers fence scatter) ------
    float smp = block_sum512(mpv, red, tid);
    float smt = block_sum512(mtv, red, tid);
    if (tid < 256) {
        a_s[tid] = mpv / (smp + EPS_DIV);
        b_s[tid] = mtv / (smt + EPS_DIV);
        u_h[tid] = __float2half_rn(KSC_U);    // u = 1
    }
    __syncthreads();

    const uint4* kt4 = (const uint4*)(smem + r * ROW_B + h * SEG_B); // K^T row r, my half
    const uint4* uh4 = (const uint4*)u_h;
    const uint4* vh4 = (const uint4*)v_h;

    unsigned short prev1 = __half_as_ushort(__float2half_rn(KSC_U));
    unsigned short prev2 = 0xFFFFu;           // u^(-1): invalid

    // ---- Phase 3: <=100 iterations, exact period-2 exit ------------------
    for (int it = 0; it < MAX_IT; ++it) {
        // -- col pass: Ktu[r] partial over my half, pair-combined ----------
        float v;
        {
            __half2 A0 = __floats2half2_rn(0.f, 0.f);
            __half2 A1 = A0, A2 = A0, A3 = A0, A4 = A0, A5 = A0, A6 = A0, A7 = A0;
            #pragma unroll
            for (int j = 0; j < 16; j += 2) {
                uint4 k0 = kt4[j];
                uint4 uu0 = uh4[16 * h + j];
                A0 = __hfma2(H2(k0.x), H2(uu0.x), A0);
                A1 = __hfma2(H2(k0.y), H2(uu0.y), A1);
                A2 = __hfma2(H2(k0.z), H2(uu0.z), A2);
                A3 = __hfma2(H2(k0.w), H2(uu0.w), A3);
                uint4 k1 = kt4[j + 1];
                uint4 uu1 = uh4[16 * h + j + 1];
                A4 = __hfma2(H2(k1.x), H2(uu1.x), A4);
                A5 = __hfma2(H2(k1.y), H2(uu1.y), A5);
                A6 = __hfma2(H2(k1.z), H2(uu1.z), A6);
                A7 = __hfma2(H2(k1.w), H2(uu1.w), A7);
            }
            float2 f0 = __half22float2(A0), f1 = __half22float2(A1);
            float2 f2 = __half22float2(A2), f3 = __half22float2(A3);
            float2 f4 = __half22float2(A4), f5 = __half22float2(A5);
            float2 f6 = __half22float2(A6), f7 = __half22float2(A7);
            float s = (((f0.x + f0.y) + (f1.x + f1.y)) + ((f2.x + f2.y) + (f3.x + f3.y)))
                    + (((f4.x + f4.y) + (f5.x + f5.y)) + ((f6.x + f6.y) + (f7.x + f7.y)));
            s += __shfl_xor_sync(0xffffffffu, s, 1);      // pair combine
            v = b_s[r] / (s * UNSC_KTU + EPS_DIV);
            if (h == 0) {
                v_s[r] = v;
                v_h[r] = __float2half_rn(v * KSC_V);
            }
        }
        __syncthreads();

        // -- row pass: Kv[r] partial from registers, pair-combined ---------
        unsigned short ubits;
        {
            __half2 R0 = __floats2half2_rn(0.f, 0.f);
            __half2 R1 = R0, R2 = R0, R3 = R0, R4 = R0, R5 = R0, R6 = R0, R7 = R0;
            #pragma unroll
            for (int j = 0; j < 16; j += 2) {
                uint4 vv0 = vh4[16 * h + j];
                R0 = __hfma2(H2(kreg[4 * j + 0]), H2(vv0.x), R0);
                R1 = __hfma2(H2(kreg[4 * j + 1]), H2(vv0.y), R1);
                R2 = __hfma2(H2(kreg[4 * j + 2]), H2(vv0.z), R2);
                R3 = __hfma2(H2(kreg[4 * j + 3]), H2(vv0.w), R3);
                uint4 vv1 = vh4[16 * h + j + 1];
                R4 = __hfma2(H2(kreg[4 * j + 4]), H2(vv1.x), R4);
                R5 = __hfma2(H2(kreg[4 * j + 5]), H2(vv1.y), R5);
                R6 = __hfma2(H2(kreg[4 * j + 6]), H2(vv1.z), R6);
                R7 = __hfma2(H2(kreg[4 * j + 7]), H2(vv1.w), R7);
            }
            float2 g0 = __half22float2(R0), g1 = __half22float2(R1);
            float2 g2 = __half22float2(R2), g3 = __half22float2(R3);
            float2 g4 = __half22float2(R4), g5 = __half22float2(R5);
            float2 g6 = __half22float2(R6), g7 = __half22float2(R7);
            float kv = (((g0.x + g0.y) + (g1.x + g1.y)) + ((g2.x + g2.y) + (g3.x + g3.y)))
                     + (((g4.x + g4.y) + (g5.x + g5.y)) + ((g6.x + g6.y) + (g7.x + g7.y)));
            kv += __shfl_xor_sync(0xffffffffu, kv, 1);    // pair combine
            float u = a_s[r] / (kv * UNSC_KV + EPS_DIV);
            __half uh = __float2half_rn(u * KSC_U);
            ubits = __half_as_ushort(uh);
            if (h == 0) {
                u_s[r] = u;
                u_h[r] = uh;
            }
        }
        // Whole-state period-2 test (parity-matched -> bit-exact skip).
        int conv = __syncthreads_and((int)(ubits == prev2));
        if (conv && (it & 1)) break;
        prev2 = prev1;
        prev1 = ubits;
    }

    // ---- Phase 4: cost from REGISTERS — no second read of C --------------
    // term = u * (t/16) * (-0.1*(ln t - ln16)) * v,  t = kreg fp16 = 16*K.
    float acc = 0.f;
    {
        const float* vsh = v_s + 128 * h;
        #pragma unroll
        for (int j = 0; j < 32; ++j) {
            float4 vv = *(const float4*)(vsh + 4 * j);
            float2 kA = __half22float2(H2(kreg[2 * j]));
            float2 kB = __half22float2(H2(kreg[2 * j + 1]));
            acc = fmaf(kA.x * (__logf(kA.x) - LN16), vv.x, acc);
            acc = fmaf(kA.y * (__logf(kA.y) - LN16), vv.y, acc);
            acc = fmaf(kB.x * (__logf(kB.x) - LN16), vv.z, acc);
            acc = fmaf(kB.y * (__logf(kB.y) - LN16), vv.w, acc);
        }
        acc *= u_s[r] * (-0.1f / 16.0f);
    }
    float tot = block_sum512(acc, red, tid);
    if (tid == 0) g_partial[b] = tot;
}

extern "C" __global__ void __launch_bounds__(256)
reduce_kernel(float* __restrict__ out)
{
    __shared__ float red[8];
    int tid = threadIdx.x;
    float s = 0.f;
    #pragma unroll
    for (int i = 0; i < BATCH / 256; ++i) s += g_partial[tid + i * 256];
    #pragma unroll
    for (int o = 16; o > 0; o >>= 1) s += __shfl_xor_sync(0xffffffffu, s, o);
    if ((tid & 31) == 0) red[tid >> 5] = s;
    __syncthreads();
    if (tid == 0) {
        float t = 0.f;
        #pragma unroll
        for (int w = 0; w < 8; ++w) t += red[w];
        out[0] = t * (1.0f / (float)BATCH);
    }
}

extern "C" void kernel_launch(void* const* d_in, const int* in_sizes, int n_in,
                              void* d_out, int out_size)
{
    const float* C  = (const float*)d_in[0];
    const float* mp = (const float*)d_in[1];
    const float* mt = (const float*)d_in[2];

    cudaFuncSetAttribute(sinkhorn_kernel,
                         cudaFuncAttributeMaxDynamicSharedMemorySize, SMEM_BYTES);
    reset_kernel<<<1, 1>>>();
    sinkhorn_kernel<<<BATCH, NT, SMEM_BYTES>>>(C, mp, mt);
    reduce_kernel<<<1, 256>>>((float*)d_out);
}